// round 16
// baseline (speedup 1.0000x reference)
#include <cuda_runtime.h>
#include <cuda_fp16.h>
#include <math.h>
#include <stdint.h>

// ---------------- problem constants ----------------
#define BATCH 256
#define SEQ   196
#define EMB   256
#define HEADS 8
#define HDIM  32
#define NBLK  4
#define FF    1024
#define NQBIT 8
#define NCLS  10
#define TOK   (BATCH*SEQ)          // 50176

// ---------------- device scratch ----------------
__device__ __half g_h[(size_t)TOK * EMB];
__device__ __half g_qkv[(size_t)TOK * 3 * EMB];
__device__ __half g_attn[(size_t)TOK * EMB];
__device__ float  g_feat[(size_t)TOK * 4];
__device__ float  g_pe[(size_t)SEQ * EMB];
__device__ __half g_w_in[(size_t)NBLK * 3 * EMB * EMB];
__device__ __half g_w_out[(size_t)NBLK * EMB * EMB];
__device__ __half g_w_l2[(size_t)NBLK * EMB * FF];

// ---------------- helpers ----------------
__device__ __forceinline__ void cp_async16(void* smem, const void* gmem) {
    unsigned s = (unsigned)__cvta_generic_to_shared(smem);
    asm volatile("cp.async.ca.shared.global [%0], [%1], 16;" :: "r"(s), "l"(gmem));
}
__device__ __forceinline__ void cp_commit() { asm volatile("cp.async.commit_group;"); }
template<int N> __device__ __forceinline__ void cp_wait() {
    asm volatile("cp.async.wait_group %0;" :: "n"(N));
}
__device__ __forceinline__ void mma_f16(float* c, const unsigned* a, unsigned b0, unsigned b1) {
    asm volatile(
        "mma.sync.aligned.m16n8k16.row.col.f32.f16.f16.f32 "
        "{%0,%1,%2,%3}, {%4,%5,%6,%7}, {%8,%9}, {%0,%1,%2,%3};"
        : "+f"(c[0]), "+f"(c[1]), "+f"(c[2]), "+f"(c[3])
        : "r"(a[0]), "r"(a[1]), "r"(a[2]), "r"(a[3]), "r"(b0), "r"(b1));
}
__device__ __forceinline__ void ldmx4(unsigned& r0, unsigned& r1, unsigned& r2, unsigned& r3,
                                      unsigned addr) {
    asm volatile("ldmatrix.sync.aligned.m8n8.x4.shared.b16 {%0,%1,%2,%3}, [%4];"
        : "=r"(r0), "=r"(r1), "=r"(r2), "=r"(r3) : "r"(addr));
}
__device__ __forceinline__ unsigned ldu(const __half* p) {
    return *(const unsigned*)(const void*)p;
}
__device__ __forceinline__ unsigned h2u(__half2 v) {
    return *(unsigned*)&v;
}

// ============================================================
// 0. merged weight fp16 conversion (one launch) + PE table
// ============================================================
__global__ void wcvt_kernel(const float* __restrict__ s0, __half* __restrict__ d0, int n0,
                            const float* __restrict__ s1, __half* __restrict__ d1, int n1,
                            const float* __restrict__ s2, __half* __restrict__ d2, int n2)
{
    int i = blockIdx.x * 256 + threadIdx.x;
    if (i < n0) d0[i] = __float2half_rn(s0[i]);
    i -= n0;
    if (i >= 0 && i < n1) d1[i] = __float2half_rn(s1[i]);
    i -= n1;
    if (i >= 0 && i < n2) d2[i] = __float2half_rn(s2[i]);
}
__global__ void pe_kernel(float* __restrict__ pe)
{
    int s = blockIdx.x, e = threadIdx.x;
    int p2 = e & ~1;
    float ang = (float)s * expf((float)p2 * (-9.210340371976184f / 256.0f));
    pe[s * EMB + e] = (e & 1) ? cosf(ang) : sinf(ang);
}

// ============================================================
// 1. Quanvolution (R11)
// ============================================================
__global__ void quanv_kernel(const float* __restrict__ x,
                             const float* __restrict__ qw,
                             const float* __restrict__ qb,
                             const float* __restrict__ pw,
                             const float* __restrict__ pb,
                             float* __restrict__ feat)
{
    int idx = blockIdx.x * 256 + threadIdx.x;
    if (idx >= TOK * 4) return;
    int c  = idx & 3;
    int s  = (idx >> 2) % SEQ;
    int b  = idx / (SEQ * 4);
    int flat = s * 4 + c;
    int ch = flat / SEQ;
    int sp = flat % SEQ;
    int i  = sp / 14, j = sp % 14;

    float acc = pb[ch];
#pragma unroll
    for (int c2 = 0; c2 < 4; c2++) {
        const float* xb = x + (((size_t)b * 4 + c2) * 28 + 2 * i) * 28 + 2 * j;
        float conv = qb[c2]
                   + xb[0]  * qw[c2 * 4 + 0]
                   + xb[1]  * qw[c2 * 4 + 1]
                   + xb[28] * qw[c2 * 4 + 2]
                   + xb[29] * qw[c2 * 4 + 3];
        acc += pw[ch * 4 + c2] * conv;
    }
    feat[idx] = acc;
}

// ============================================================
// 2. Embedding + PE — output fp16 (R11)
// ============================================================
__global__ void embed_kernel(const float* __restrict__ feat,
                             const float* __restrict__ ew,
                             const float* __restrict__ eb,
                             const float* __restrict__ pe,
                             __half* __restrict__ h)
{
    int m = blockIdx.x;
    int e = threadIdx.x;
    float4 f = *(const float4*)(feat + (size_t)m * 4);
    float4 w = *(const float4*)(ew + (size_t)e * 4);
    float acc = eb[e] + f.x * w.x + f.y * w.y + f.z * w.z + f.w * w.w;
    acc += pe[(m % SEQ) * EMB + e];
    h[(size_t)m * EMB + e] = __float2half_rn(acc);
}

// ============================================================
// 3. fp16 tensor-core GEMM, CTA 128x256, 8 warps @ 64x64, K-chunk 64,
//    ldmatrix fragment loads, 2-stage pipeline. (R11 config — known good)
// ============================================================
#define GKH 72
#define SA_BYTES (128*GKH*2)                 // 18432
#define SB_BYTES (256*GKH*2)                 // 36864
#define OFF_SRED  0
#define OFF_BIAS  4096
#define OFF_G     5120
#define OFF_BL    6144
#define OFF_QM    7168
#define OFF_SL    11264
#define OFF_SLB   15360
#define OFF_SA    15872
#define OFF_SB    (OFF_SA + 2*SA_BYTES)      // 52736
#define SMEM_GH   (OFF_SB + 2*SB_BYTES)      // 126464 B

template<int ASRC>
__device__ __forceinline__ void stage_chunk(const __half* __restrict__ A,
                                            const __half* __restrict__ W,
                                            char* smc, int bm, int bn, int K,
                                            int cc, int buf, int tid)
{
    const __half* Wg = W + (size_t)(bn + tid) * K + cc * 64;
    char* bw = smc + OFF_SB + buf * SB_BYTES + tid * (GKH * 2);
#pragma unroll
    for (int q = 0; q < 8; q++) cp_async16(bw + q * 16, Wg + q * 8);
    if (ASRC == 0) {
        int m = tid >> 1, hf = tid & 1;
        const __half* Ag = A + (size_t)(bm + m) * K + cc * 64 + hf * 32;
        char* aw = smc + OFF_SA + buf * SA_BYTES + m * (GKH * 2) + hf * 64;
#pragma unroll
        for (int q = 0; q < 4; q++) cp_async16(aw + q * 16, Ag + q * 8);
    }
}

__device__ __forceinline__ void compute_a_chunk64(char* smc, int buf, int slbuf, int tid)
{
    const float* qm  = (const float*)(smc + OFF_QM);
    const float* sL  = (const float*)(smc + OFF_SL);
    const float* slb = (const float*)(smc + OFF_SLB);
    int m = tid >> 1, kb = (tid & 1) * 32;
    float qv[8];
    *(float4*)qv       = *(const float4*)(qm + m * 8);
    *(float4*)(qv + 4) = *(const float4*)(qm + m * 8 + 4);
    unsigned outp[16];
#pragma unroll
    for (int j2 = 0; j2 < 16; j2++) {
        float v01[2];
#pragma unroll
        for (int e = 0; e < 2; e++) {
            int kl = kb + j2 * 2 + e;
            const float* lr = sL + slbuf * 512 + kl * 8;
            float v = slb[slbuf * 64 + kl];
#pragma unroll
            for (int q = 0; q < 8; q++) v += qv[q] * lr[q];
            v01[e] = fmaxf(v, 0.f);
        }
        outp[j2] = h2u(__floats2half2_rn(v01[0], v01[1]));
    }
    char* aw = smc + OFF_SA + buf * SA_BYTES + m * (GKH * 2) + kb * 2;
#pragma unroll
    for (int q4 = 0; q4 < 4; q4++)
        *(uint4*)(aw + q4 * 16) = make_uint4(outp[q4 * 4], outp[q4 * 4 + 1],
                                             outp[q4 * 4 + 2], outp[q4 * 4 + 3]);
}

template<int ASRC, int EPI>
__global__ void __launch_bounds__(256, 1)
gemm_h(const __half* __restrict__ A, const __half* __restrict__ W,
       const float* __restrict__ bias, const __half* __restrict__ resid,
       const float* __restrict__ lng, const float* __restrict__ lnbb,
       const float* __restrict__ l1w, const float* __restrict__ l1b,
       const float* __restrict__ theta,
       __half* __restrict__ C, int M, int N, int K)
{
    extern __shared__ char smc[];
    float2* sred  = (float2*)(smc + OFF_SRED);
    float*  sbias = (float*)(smc + OFF_BIAS);
    float*  sg    = (float*)(smc + OFF_G);
    float*  sbl   = (float*)(smc + OFF_BL);
    float*  qm    = (float*)(smc + OFF_QM);
    float*  sL    = (float*)(smc + OFF_SL);
    float*  slb   = (float*)(smc + OFF_SLB);

    const int tid  = threadIdx.x;
    const int lane = tid & 31;
    const int wid  = tid >> 5;
    const int bm   = blockIdx.y * 128;
    const int bn   = blockIdx.x * 256;
    const int wm   = (wid & 1) * 64;
    const int wn   = (wid >> 1) * 64;
    const int ln4  = lane >> 2;
    const int lnm  = lane & 3;
    const unsigned su = (unsigned)__cvta_generic_to_shared(smc);

    const int a_row = lane & 15;
    const int a_kq  = (lane >> 4) << 3;
    const int b_row = (lane & 7) + (((lane >> 4) & 1) << 3);
    const int b_kq  = ((lane >> 3) & 1) << 3;

    sbias[tid] = bias[bn + tid];
    if (EPI == 1) { sg[tid] = lng[tid]; sbl[tid] = lnbb[tid]; }

    if (ASRC == 1) {
        if (tid < 128) {
            const __half* hp = A + (size_t)(bm + tid) * EMB;
#pragma unroll
            for (int q = 0; q < 8; q++)
                qm[tid * 8 + q] = cosf(__half2float(hp[q])) * cosf(theta[q]);
        }
        if (tid < 128) {
            int rr = tid >> 1, hf = (tid & 1) * 4;
            *(float4*)(sL + rr * 8 + hf) = *(const float4*)(l1w + rr * 8 + hf);
        }
        if (tid < 64) slb[tid] = l1b[tid];
    }

    float acc[4][8][4];
#pragma unroll
    for (int i = 0; i < 4; i++)
#pragma unroll
        for (int j = 0; j < 8; j++)
#pragma unroll
            for (int t = 0; t < 4; t++) acc[i][j][t] = 0.f;

    const int nc = K >> 6;

    stage_chunk<ASRC>(A, W, smc, bm, bn, K, 0, 0, tid);
    cp_commit();
    if (ASRC == 1) {
        __syncthreads();
        compute_a_chunk64(smc, 0, 0, tid);
    }

    for (int c = 0; c < nc; c++) {
        const int buf = c & 1;
        const int nb  = buf ^ 1;
        if (c + 1 < nc) {
            stage_chunk<ASRC>(A, W, smc, bm, bn, K, c + 1, nb, tid);
            if (ASRC == 1) {
                if (tid < 128) {
                    int rr = tid >> 1, hf = (tid & 1) * 4;
                    *(float4*)(sL + ((c + 1) & 1) * 512 + rr * 8 + hf) =
                        *(const float4*)(l1w + ((size_t)(c + 1) * 64 + rr) * 8 + hf);
                }
                if (tid < 64) slb[((c + 1) & 1) * 64 + tid] = l1b[(c + 1) * 64 + tid];
            }
            cp_commit();
            cp_wait<1>();
        } else {
            cp_wait<0>();
        }
        __syncthreads();

        const unsigned abase = su + OFF_SA + buf * SA_BYTES;
        const unsigned bbase = su + OFF_SB + buf * SB_BYTES;

#pragma unroll
        for (int s = 0; s < 4; s++) {
            const int k0 = s * 16;
            unsigned af[4][4];
#pragma unroll
            for (int i = 0; i < 4; i++) {
                unsigned addr = abase +
                    ((wm + i * 16 + a_row) * GKH + k0 + a_kq) * 2;
                ldmx4(af[i][0], af[i][1], af[i][2], af[i][3], addr);
            }
#pragma unroll
            for (int j2 = 0; j2 < 4; j2++) {
                unsigned baddr = bbase +
                    ((wn + j2 * 16 + b_row) * GKH + k0 + b_kq) * 2;
                unsigned b0, b1, b2, b3;
                ldmx4(b0, b1, b2, b3, baddr);
#pragma unroll
                for (int i = 0; i < 4; i++) {
                    mma_f16(acc[i][2 * j2],     af[i], b0, b1);
                    mma_f16(acc[i][2 * j2 + 1], af[i], b2, b3);
                }
            }
        }

        if (ASRC == 1 && c + 1 < nc)
            compute_a_chunk64(smc, nb, (c + 1) & 1, tid);
        __syncthreads();
    }

    if (EPI == 0) {
#pragma unroll
        for (int i = 0; i < 4; i++) {
            const int gr0 = bm + wm + i * 16 + ln4;
#pragma unroll
            for (int j = 0; j < 8; j++) {
                const int col = wn + j * 8 + 2 * lnm;
                const float b0 = sbias[col], b1 = sbias[col + 1];
                *(__half2*)(C + (size_t)gr0 * N + bn + col) =
                    __floats2half2_rn(acc[i][j][0] + b0, acc[i][j][1] + b1);
                *(__half2*)(C + (size_t)(gr0 + 8) * N + bn + col) =
                    __floats2half2_rn(acc[i][j][2] + b0, acc[i][j][3] + b1);
            }
        }
    } else {
#pragma unroll
        for (int i = 0; i < 4; i++) {
            const int lr0 = wm + i * 16 + ln4;
            const int gr0 = bm + lr0;
            float s0 = 0.f, q0 = 0.f, s1 = 0.f, q1 = 0.f;
#pragma unroll
            for (int j = 0; j < 8; j++) {
                const int col = wn + j * 8 + 2 * lnm;
                const float b0 = sbias[col], b1 = sbias[col + 1];
                float2 r0 = __half22float2(*(const __half2*)(resid + (size_t)gr0 * 256 + col));
                float2 r1 = __half22float2(*(const __half2*)(resid + (size_t)(gr0 + 8) * 256 + col));
                float v0 = acc[i][j][0] + b0 + r0.x;
                float v1 = acc[i][j][1] + b1 + r0.y;
                float v2 = acc[i][j][2] + b0 + r1.x;
                float v3 = acc[i][j][3] + b1 + r1.y;
                acc[i][j][0] = v0; acc[i][j][1] = v1;
                acc[i][j][2] = v2; acc[i][j][3] = v3;
                s0 += v0 + v1; q0 += v0 * v0 + v1 * v1;
                s1 += v2 + v3; q1 += v2 * v2 + v3 * v3;
            }
#pragma unroll
            for (int o = 1; o <= 2; o <<= 1) {
                s0 += __shfl_xor_sync(0xffffffffu, s0, o);
                q0 += __shfl_xor_sync(0xffffffffu, q0, o);
                s1 += __shfl_xor_sync(0xffffffffu, s1, o);
                q1 += __shfl_xor_sync(0xffffffffu, q1, o);
            }
            if (lnm == 0) {
                sred[lr0 * 4 + (wid >> 1)]       = make_float2(s0, q0);
                sred[(lr0 + 8) * 4 + (wid >> 1)] = make_float2(s1, q1);
            }
        }
        __syncthreads();
#pragma unroll
        for (int i = 0; i < 4; i++) {
            const int lr0 = wm + i * 16 + ln4;
            const int gr0 = bm + lr0;
            float2 a0 = sred[lr0 * 4 + 0], a1 = sred[lr0 * 4 + 1];
            float2 a2 = sred[lr0 * 4 + 2], a3 = sred[lr0 * 4 + 3];
            float mean0 = (a0.x + a1.x + a2.x + a3.x) * (1.f / 256.f);
            float e0    = (a0.y + a1.y + a2.y + a3.y) * (1.f / 256.f);
            float rstd0 = rsqrtf(e0 - mean0 * mean0 + 1e-5f);
            float2 c0 = sred[(lr0 + 8) * 4 + 0], c1 = sred[(lr0 + 8) * 4 + 1];
            float2 c2 = sred[(lr0 + 8) * 4 + 2], c3 = sred[(lr0 + 8) * 4 + 3];
            float mean1 = (c0.x + c1.x + c2.x + c3.x) * (1.f / 256.f);
            float e1    = (c0.y + c1.y + c2.y + c3.y) * (1.f / 256.f);
            float rstd1 = rsqrtf(e1 - mean1 * mean1 + 1e-5f);
#pragma unroll
            for (int j = 0; j < 8; j++) {
                const int col = wn + j * 8 + 2 * lnm;
                const float g0 = sg[col], g1 = sg[col + 1];
                const float d0 = sbl[col], d1 = sbl[col + 1];
                *(__half2*)(C + (size_t)gr0 * 256 + col) = __floats2half2_rn(
                    (acc[i][j][0] - mean0) * rstd0 * g0 + d0,
                    (acc[i][j][1] - mean0) * rstd0 * g1 + d1);
                *(__half2*)(C + (size_t)(gr0 + 8) * 256 + col) = __floats2half2_rn(
                    (acc[i][j][2] - mean1) * rstd1 * g0 + d0,
                    (acc[i][j][3] - mean1) * rstd1 * g1 + d1);
            }
        }
    }
}

// ============================================================
// 4. fp16 tensor-core attention — online softmax, occ 2 (R11) with
//    vectorized half2 V staging.
// ============================================================
#define KS_ST 40
#define VT_ST 216
#define PS_ST 72

__global__ void __launch_bounds__(256, 2)
attention_h(const __half* __restrict__ qkv, __half* __restrict__ o)
{
    __shared__ __half Ks[208 * KS_ST];
    __shared__ __half Vt[32 * VT_ST];
    __shared__ __half Ps[8 * 16 * PS_ST];

    const int hh = blockIdx.x;
    const int b  = blockIdx.y;
    const int tid  = threadIdx.x;
    const int lane = tid & 31;
    const int wid  = tid >> 5;
    const int r    = lane >> 2;
    const int lq   = lane & 3;
    const float scale = 0.17677669529663687f;
    const __half* base = qkv + (size_t)b * SEQ * (3 * EMB) + hh * HDIM;

    const int a_row = lane & 15;
    const int a_kq  = (lane >> 4) << 3;
    const int b_row = (lane & 7) + (((lane >> 4) & 1) << 3);
    const int b_kq  = ((lane >> 3) & 1) << 3;

    for (int i = tid; i < 208 * 4; i += 256) {
        int s = i >> 2, sg = i & 3;
        float4 v = make_float4(0.f, 0.f, 0.f, 0.f);
        if (s < SEQ) v = *(const float4*)(base + (size_t)s * (3 * EMB) + EMB + sg * 8);
        *(float4*)(Ks + s * KS_ST + sg * 8) = v;
    }
    // V transpose: half2 loads (2 dims per thread), scatter to 2 smem rows
    for (int i = tid; i < SEQ * 16; i += 256) {
        int s = i >> 4, d2 = (i & 15) * 2;
        __half2 v = *(const __half2*)(base + (size_t)s * (3 * EMB) + 2 * EMB + d2);
        Vt[d2 * VT_ST + s]       = __low2half(v);
        Vt[(d2 + 1) * VT_ST + s] = __high2half(v);
    }
    for (int i = tid; i < 32 * 20; i += 256) {
        int d = i / 20, c = SEQ + i % 20;
        Vt[d * VT_ST + c] = __float2half(0.f);
    }
    __syncthreads();

    __half* Pw = Ps + wid * 16 * PS_ST;
    const unsigned ks_su = (unsigned)__cvta_generic_to_shared(Ks);
    const unsigned vt_su = (unsigned)__cvta_generic_to_shared(Vt);
    const unsigned pw_su = (unsigned)__cvta_generic_to_shared(Pw);

    for (int strip = wid; strip < 13; strip += 8) {
        const int q0 = strip * 16 + r;
        const int q1 = q0 + 8;
        const int qa = q0 < SEQ ? q0 : SEQ - 1;
        const int qb = q1 < SEQ ? q1 : SEQ - 1;

        unsigned af[2][4];
#pragma unroll
        for (int kc = 0; kc < 2; kc++) {
            const __half* pa = base + (size_t)qa * (3 * EMB) + kc * 16 + 2 * lq;
            const __half* pc = base + (size_t)qb * (3 * EMB) + kc * 16 + 2 * lq;
            af[kc][0] = ldu(pa);
            af[kc][1] = ldu(pc);
            af[kc][2] = ldu(pa + 8);
            af[kc][3] = ldu(pc + 8);
        }

        float m0 = -1e30f, m1 = -1e30f;
        float l0 = 0.f,   l1 = 0.f;
        float O[4][4];
#pragma unroll
        for (int nt = 0; nt < 4; nt++) {
            O[nt][0] = 0.f; O[nt][1] = 0.f; O[nt][2] = 0.f; O[nt][3] = 0.f;
        }

#pragma unroll
        for (int ch = 0; ch < 4; ch++) {
            const int njg = (ch < 3) ? 8 : 2;
            const int njp = (ch < 3) ? 4 : 1;

            float acc[8][4];
#pragma unroll
            for (int jj = 0; jj < 8; jj++) {
                acc[jj][0] = 0.f; acc[jj][1] = 0.f;
                acc[jj][2] = 0.f; acc[jj][3] = 0.f;
            }
#pragma unroll
            for (int jpl = 0; jpl < 4; jpl++) {
                if (jpl < njp) {
                    const int jp = ch * 4 + jpl;
#pragma unroll
                    for (int kc = 0; kc < 2; kc++) {
                        unsigned baddr = ks_su +
                            ((jp * 16 + b_row) * KS_ST + kc * 16 + b_kq) * 2;
                        unsigned b0, b1, b2, b3;
                        ldmx4(b0, b1, b2, b3, baddr);
                        mma_f16(acc[2 * jpl],     af[kc], b0, b1);
                        mma_f16(acc[2 * jpl + 1], af[kc], b2, b3);
                    }
                }
            }
            if (ch == 3) {
                if (lq >= 2) {
                    acc[0][0] = -1e30f; acc[0][1] = -1e30f;
                    acc[0][2] = -1e30f; acc[0][3] = -1e30f;
                }
                acc[1][0] = -1e30f; acc[1][1] = -1e30f;
                acc[1][2] = -1e30f; acc[1][3] = -1e30f;
            }

            float lm0 = -1e30f, lm1 = -1e30f;
#pragma unroll
            for (int jj = 0; jj < 8; jj++) {
                if (jj < njg) {
                    lm0 = fmaxf(lm0, fmaxf(acc[jj][0], acc[jj][1]));
                    lm1 = fmaxf(lm1, fmaxf(acc[jj][2], acc[jj][3]));
                }
            }
            lm0 = fmaxf(lm0, __shfl_xor_sync(0xffffffffu, lm0, 1));
            lm0 = fmaxf(lm0, __shfl_xor_sync(0xffffffffu, lm0, 2));
            lm1 = fmaxf(lm1, __shfl_xor_sync(0xffffffffu, lm1, 1));
            lm1 = fmaxf(lm1, __shfl_xor_sync(0xffffffffu, lm1, 2));
            const float mn0 = fmaxf(m0, lm0);
            const float mn1 = fmaxf(m1, lm1);
            const float f0 = __expf((m0 - mn0) * scale);
            const float f1 = __expf((m1 - mn1) * scale);
            m0 = mn0; m1 = mn1;

            float s0 = 0.f, s1 = 0.f;
#pragma unroll
            for (int jj = 0; jj < 8; jj++) {
                if (jj < njg) {
                    acc[jj][0] = __expf((acc[jj][0] - mn0) * scale);
                    acc[jj][1] = __expf((acc[jj][1] - mn0) * scale);
                    acc[jj][2] = __expf((acc[jj][2] - mn1) * scale);
                    acc[jj][3] = __expf((acc[jj][3] - mn1) * scale);
                    s0 += acc[jj][0] + acc[jj][1];
                    s1 += acc[jj][2] + acc[jj][3];
                }
            }
            s0 += __shfl_xor_sync(0xffffffffu, s0, 1);
            s0 += __shfl_xor_sync(0xffffffffu, s0, 2);
            s1 += __shfl_xor_sync(0xffffffffu, s1, 1);
            s1 += __shfl_xor_sync(0xffffffffu, s1, 2);
            l0 = l0 * f0 + s0;
            l1 = l1 * f1 + s1;
#pragma unroll
            for (int nt = 0; nt < 4; nt++) {
                O[nt][0] *= f0; O[nt][1] *= f0;
                O[nt][2] *= f1; O[nt][3] *= f1;
            }

#pragma unroll
            for (int jj = 0; jj < 8; jj++) {
                if (jj < njg) {
                    *(__half2*)(Pw + r * PS_ST + jj * 8 + 2 * lq) =
                        __floats2half2_rn(acc[jj][0], acc[jj][1]);
                    *(__half2*)(Pw + (r + 8) * PS_ST + jj * 8 + 2 * lq) =
                        __floats2half2_rn(acc[jj][2], acc[jj][3]);
                }
            }
            __syncwarp();
            const int nkk = (ch < 3) ? 4 : 1;
#pragma unroll
            for (int kk = 0; kk < 4; kk++) {
                if (kk < nkk) {
                    unsigned pa[4];
                    unsigned paddr = pw_su + (a_row * PS_ST + kk * 16 + a_kq) * 2;
                    ldmx4(pa[0], pa[1], pa[2], pa[3], paddr);
#pragma unroll
                    for (int ntp = 0; ntp < 2; ntp++) {
                        unsigned vaddr = vt_su +
                            ((ntp * 16 + b_row) * VT_ST + ch * 64 + kk * 16 + b_kq) * 2;
                        unsigned b0, b1, b2, b3;
                        ldmx4(b0, b1, b2, b3, vaddr);
                        mma_f16(O[2 * ntp],     pa, b0, b1);
                        mma_f16(O[2 * ntp + 1], pa, b2, b3);
                    }
                }
            }
            __syncwarp();
        }

        const float inv0 = 1.f / l0;
        const float inv1 = 1.f / l1;

        if (q0 < SEQ) {
            __half* op = o + (size_t)(b * SEQ + q0) * EMB + hh * HDIM + 2 * lq;
#pragma unroll
            for (int nt = 0; nt < 4; nt++)
                *(__half2*)(op + nt * 8) =
                    __floats2half2_rn(O[nt][0] * inv0, O[nt][1] * inv0);
        }
        if (q1 < SEQ) {
            __half* op = o + (size_t)(b * SEQ + q1) * EMB + hh * HDIM + 2 * lq;
#pragma unroll
            for (int nt = 0; nt < 4; nt++)
                *(__half2*)(op + nt * 8) =
                    __floats2half2_rn(O[nt][2] * inv1, O[nt][3] * inv1);
        }
    }
}

// ============================================================
// 7. Mean-pool + classifier (h is fp16)
// ============================================================
__global__ void __launch_bounds__(256)
pool_cls_kernel(const __half* __restrict__ h, const float* __restrict__ cw,
                const float* __restrict__ cb, float* __restrict__ out)
{
    int b = blockIdx.x;
    int e = threadIdx.x;
    const __half* hp = h + (size_t)b * SEQ * EMB + e;
    float s = 0.f;
    for (int t = 0; t < SEQ; t++) s += __half2float(hp[(size_t)t * EMB]);
    __shared__ float sp[EMB];
    sp[e] = s * (1.f / 196.f);
    __syncthreads();
    if (e < NCLS) {
        float acc = cb[e];
        const float* w = cw + e * EMB;
        for (int k = 0; k < EMB; k++) acc += sp[k] * w[k];
        out[b * NCLS + e] = acc;
    }
}

// ============================================================
// launcher
// ============================================================
extern "C" void kernel_launch(void* const* d_in, const int* in_sizes, int n_in,
                              void* d_out, int out_size)
{
    const float* x    = (const float*)d_in[0];
    const float* qfw  = (const float*)d_in[1];
    const float* qfb  = (const float*)d_in[2];
    const float* pww  = (const float*)d_in[3];
    const float* pwb  = (const float*)d_in[4];
    const float* embw = (const float*)d_in[5];
    const float* embb = (const float*)d_in[6];
    const float* inw  = (const float*)d_in[7];
    const float* inb  = (const float*)d_in[8];
    const float* outw = (const float*)d_in[9];
    const float* outb = (const float*)d_in[10];
    const float* thet = (const float*)d_in[11];
    const float* l1w  = (const float*)d_in[12];
    const float* l1b  = (const float*)d_in[13];
    const float* l2w  = (const float*)d_in[14];
    const float* l2b  = (const float*)d_in[15];
    const float* ln1g = (const float*)d_in[16];
    const float* ln1b = (const float*)d_in[17];
    const float* ln2g = (const float*)d_in[18];
    const float* ln2b = (const float*)d_in[19];
    const float* clsw = (const float*)d_in[20];
    const float* clsb = (const float*)d_in[21];
    float* out = (float*)d_out;

    __half *h, *qkv, *attn, *w_in, *w_out, *w_l2;
    float *feat, *pe;
    cudaGetSymbolAddress((void**)&h,     g_h);
    cudaGetSymbolAddress((void**)&qkv,   g_qkv);
    cudaGetSymbolAddress((void**)&attn,  g_attn);
    cudaGetSymbolAddress((void**)&feat,  g_feat);
    cudaGetSymbolAddress((void**)&pe,    g_pe);
    cudaGetSymbolAddress((void**)&w_in,  g_w_in);
    cudaGetSymbolAddress((void**)&w_out, g_w_out);
    cudaGetSymbolAddress((void**)&w_l2,  g_w_l2);

    cudaFuncSetAttribute(gemm_h<0,0>,
                         cudaFuncAttributeMaxDynamicSharedMemorySize, SMEM_GH);
    cudaFuncSetAttribute(gemm_h<0,1>,
                         cudaFuncAttributeMaxDynamicSharedMemorySize, SMEM_GH);
    cudaFuncSetAttribute(gemm_h<1,1>,
                         cudaFuncAttributeMaxDynamicSharedMemorySize, SMEM_GH);

    const int n_in_w  = NBLK * 3 * EMB * EMB;
    const int n_out_w = NBLK * EMB * EMB;
    const int n_l2_w  = NBLK * EMB * FF;
    const int n_tot   = n_in_w + n_out_w + n_l2_w;
    wcvt_kernel<<<(n_tot + 255) / 256, 256>>>(inw, w_in, n_in_w,
                                              outw, w_out, n_out_w,
                                              l2w, w_l2, n_l2_w);
    pe_kernel<<<SEQ, EMB>>>(pe);

    quanv_kernel<<<(TOK * 4 + 255) / 256, 256>>>(x, qfw, qfb, pww, pwb, feat);
    embed_kernel<<<TOK, 256>>>(feat, embw, embb, pe, h);

    for (int i = 0; i < NBLK; i++) {
        gemm_h<0,0><<<dim3(3, TOK / 128), 256, SMEM_GH>>>(
            h, w_in + (size_t)i * 3 * EMB * EMB, inb + (size_t)i * 3 * EMB,
            nullptr, nullptr, nullptr, nullptr, nullptr, nullptr,
            qkv, TOK, 3 * EMB, EMB);

        attention_h<<<dim3(HEADS, BATCH), 256>>>(qkv, attn);

        gemm_h<0,1><<<dim3(1, TOK / 128), 256, SMEM_GH>>>(
            attn, w_out + (size_t)i * EMB * EMB, outb + (size_t)i * EMB,
            h, ln1g + (size_t)i * EMB, ln1b + (size_t)i * EMB,
            nullptr, nullptr, nullptr,
            h, TOK, EMB, EMB);

        gemm_h<1,1><<<dim3(1, TOK / 128), 256, SMEM_GH>>>(
            h, w_l2 + (size_t)i * EMB * FF, l2b + (size_t)i * EMB,
            h, ln2g + (size_t)i * EMB, ln2b + (size_t)i * EMB,
            l1w + (size_t)i * FF * NQBIT, l1b + (size_t)i * FF,
            thet + (size_t)i * NQBIT,
            h, TOK, EMB, FF);
    }

    pool_cls_kernel<<<BATCH, 256>>>(h, clsw, clsb, out);
}

// round 17
// speedup vs baseline: 1.0389x; 1.0389x over previous
#include <cuda_runtime.h>
#include <cuda_fp16.h>
#include <math.h>
#include <stdint.h>

// ---------------- problem constants ----------------
#define BATCH 256
#define SEQ   196
#define EMB   256
#define HEADS 8
#define HDIM  32
#define NBLK  4
#define FF    1024
#define NQBIT 8
#define NCLS  10
#define TOK   (BATCH*SEQ)          // 50176

// ---------------- device scratch ----------------
__device__ __half g_h[(size_t)TOK * EMB];
__device__ __half g_qkv[(size_t)TOK * 3 * EMB];
__device__ __half g_attn[(size_t)TOK * EMB];
__device__ float  g_feat[(size_t)TOK * 4];
__device__ float  g_pe[(size_t)SEQ * EMB];
__device__ __half g_w_in[(size_t)NBLK * 3 * EMB * EMB];
__device__ __half g_w_out[(size_t)NBLK * EMB * EMB];
__device__ __half g_w_l2[(size_t)NBLK * EMB * FF];

// ---------------- helpers ----------------
__device__ __forceinline__ void cp_async16(void* smem, const void* gmem) {
    unsigned s = (unsigned)__cvta_generic_to_shared(smem);
    asm volatile("cp.async.ca.shared.global [%0], [%1], 16;" :: "r"(s), "l"(gmem));
}
__device__ __forceinline__ void cp_commit() { asm volatile("cp.async.commit_group;"); }
template<int N> __device__ __forceinline__ void cp_wait() {
    asm volatile("cp.async.wait_group %0;" :: "n"(N));
}
__device__ __forceinline__ void mma_f16(float* c, const unsigned* a, unsigned b0, unsigned b1) {
    asm volatile(
        "mma.sync.aligned.m16n8k16.row.col.f32.f16.f16.f32 "
        "{%0,%1,%2,%3}, {%4,%5,%6,%7}, {%8,%9}, {%0,%1,%2,%3};"
        : "+f"(c[0]), "+f"(c[1]), "+f"(c[2]), "+f"(c[3])
        : "r"(a[0]), "r"(a[1]), "r"(a[2]), "r"(a[3]), "r"(b0), "r"(b1));
}
__device__ __forceinline__ void ldmx4(unsigned& r0, unsigned& r1, unsigned& r2, unsigned& r3,
                                      unsigned addr) {
    asm volatile("ldmatrix.sync.aligned.m8n8.x4.shared.b16 {%0,%1,%2,%3}, [%4];"
        : "=r"(r0), "=r"(r1), "=r"(r2), "=r"(r3) : "r"(addr));
}
__device__ __forceinline__ unsigned ldu(const __half* p) {
    return *(const unsigned*)(const void*)p;
}
__device__ __forceinline__ unsigned h2u(__half2 v) {
    return *(unsigned*)&v;
}

// ============================================================
// 0. merged weight fp16 conversion (one launch) + PE table
// ============================================================
__global__ void wcvt_kernel(const float* __restrict__ s0, __half* __restrict__ d0, int n0,
                            const float* __restrict__ s1, __half* __restrict__ d1, int n1,
                            const float* __restrict__ s2, __half* __restrict__ d2, int n2)
{
    int i = blockIdx.x * 256 + threadIdx.x;
    if (i < n0) d0[i] = __float2half_rn(s0[i]);
    i -= n0;
    if (i >= 0 && i < n1) d1[i] = __float2half_rn(s1[i]);
    i -= n1;
    if (i >= 0 && i < n2) d2[i] = __float2half_rn(s2[i]);
}
__global__ void pe_kernel(float* __restrict__ pe)
{
    int s = blockIdx.x, e = threadIdx.x;
    int p2 = e & ~1;
    float ang = (float)s * expf((float)p2 * (-9.210340371976184f / 256.0f));
    pe[s * EMB + e] = (e & 1) ? cosf(ang) : sinf(ang);
}

// ============================================================
// 1. Quanvolution (R11)
// ============================================================
__global__ void quanv_kernel(const float* __restrict__ x,
                             const float* __restrict__ qw,
                             const float* __restrict__ qb,
                             const float* __restrict__ pw,
                             const float* __restrict__ pb,
                             float* __restrict__ feat)
{
    int idx = blockIdx.x * 256 + threadIdx.x;
    if (idx >= TOK * 4) return;
    int c  = idx & 3;
    int s  = (idx >> 2) % SEQ;
    int b  = idx / (SEQ * 4);
    int flat = s * 4 + c;
    int ch = flat / SEQ;
    int sp = flat % SEQ;
    int i  = sp / 14, j = sp % 14;

    float acc = pb[ch];
#pragma unroll
    for (int c2 = 0; c2 < 4; c2++) {
        const float* xb = x + (((size_t)b * 4 + c2) * 28 + 2 * i) * 28 + 2 * j;
        float conv = qb[c2]
                   + xb[0]  * qw[c2 * 4 + 0]
                   + xb[1]  * qw[c2 * 4 + 1]
                   + xb[28] * qw[c2 * 4 + 2]
                   + xb[29] * qw[c2 * 4 + 3];
        acc += pw[ch * 4 + c2] * conv;
    }
    feat[idx] = acc;
}

// ============================================================
// 2. Embedding + PE — 4 tokens per block, ew row reused 4x.
// ============================================================
__global__ void __launch_bounds__(256)
embed_kernel(const float* __restrict__ feat,
             const float* __restrict__ ew,
             const float* __restrict__ eb,
             const float* __restrict__ pe,
             __half* __restrict__ h)
{
    const int m0 = blockIdx.x * 4;
    const int e  = threadIdx.x;
    float4 w = *(const float4*)(ew + (size_t)e * 4);
    float  b = eb[e];
#pragma unroll
    for (int t = 0; t < 4; t++) {
        const int m = m0 + t;
        float4 f = *(const float4*)(feat + (size_t)m * 4);
        float acc = b + f.x * w.x + f.y * w.y + f.z * w.z + f.w * w.w;
        acc += pe[(m % SEQ) * EMB + e];
        h[(size_t)m * EMB + e] = __float2half_rn(acc);
    }
}

// ============================================================
// 3. fp16 tensor-core GEMM, CTA 128x256, 8 warps @ 64x64, K-chunk 64,
//    ldmatrix fragment loads, 2-stage pipeline. (R11 config — known good)
// ============================================================
#define GKH 72
#define SA_BYTES (128*GKH*2)                 // 18432
#define SB_BYTES (256*GKH*2)                 // 36864
#define OFF_SRED  0
#define OFF_BIAS  4096
#define OFF_G     5120
#define OFF_BL    6144
#define OFF_QM    7168
#define OFF_SL    11264
#define OFF_SLB   15360
#define OFF_SA    15872
#define OFF_SB    (OFF_SA + 2*SA_BYTES)      // 52736
#define SMEM_GH   (OFF_SB + 2*SB_BYTES)      // 126464 B

template<int ASRC>
__device__ __forceinline__ void stage_chunk(const __half* __restrict__ A,
                                            const __half* __restrict__ W,
                                            char* smc, int bm, int bn, int K,
                                            int cc, int buf, int tid)
{
    const __half* Wg = W + (size_t)(bn + tid) * K + cc * 64;
    char* bw = smc + OFF_SB + buf * SB_BYTES + tid * (GKH * 2);
#pragma unroll
    for (int q = 0; q < 8; q++) cp_async16(bw + q * 16, Wg + q * 8);
    if (ASRC == 0) {
        int m = tid >> 1, hf = tid & 1;
        const __half* Ag = A + (size_t)(bm + m) * K + cc * 64 + hf * 32;
        char* aw = smc + OFF_SA + buf * SA_BYTES + m * (GKH * 2) + hf * 64;
#pragma unroll
        for (int q = 0; q < 4; q++) cp_async16(aw + q * 16, Ag + q * 8);
    }
}

__device__ __forceinline__ void compute_a_chunk64(char* smc, int buf, int slbuf, int tid)
{
    const float* qm  = (const float*)(smc + OFF_QM);
    const float* sL  = (const float*)(smc + OFF_SL);
    const float* slb = (const float*)(smc + OFF_SLB);
    int m = tid >> 1, kb = (tid & 1) * 32;
    float qv[8];
    *(float4*)qv       = *(const float4*)(qm + m * 8);
    *(float4*)(qv + 4) = *(const float4*)(qm + m * 8 + 4);
    unsigned outp[16];
#pragma unroll
    for (int j2 = 0; j2 < 16; j2++) {
        float v01[2];
#pragma unroll
        for (int e = 0; e < 2; e++) {
            int kl = kb + j2 * 2 + e;
            const float* lr = sL + slbuf * 512 + kl * 8;
            float v = slb[slbuf * 64 + kl];
#pragma unroll
            for (int q = 0; q < 8; q++) v += qv[q] * lr[q];
            v01[e] = fmaxf(v, 0.f);
        }
        outp[j2] = h2u(__floats2half2_rn(v01[0], v01[1]));
    }
    char* aw = smc + OFF_SA + buf * SA_BYTES + m * (GKH * 2) + kb * 2;
#pragma unroll
    for (int q4 = 0; q4 < 4; q4++)
        *(uint4*)(aw + q4 * 16) = make_uint4(outp[q4 * 4], outp[q4 * 4 + 1],
                                             outp[q4 * 4 + 2], outp[q4 * 4 + 3]);
}

template<int ASRC, int EPI>
__global__ void __launch_bounds__(256, 1)
gemm_h(const __half* __restrict__ A, const __half* __restrict__ W,
       const float* __restrict__ bias, const __half* __restrict__ resid,
       const float* __restrict__ lng, const float* __restrict__ lnbb,
       const float* __restrict__ l1w, const float* __restrict__ l1b,
       const float* __restrict__ theta,
       __half* __restrict__ C, int M, int N, int K)
{
    extern __shared__ char smc[];
    float2* sred  = (float2*)(smc + OFF_SRED);
    float*  sbias = (float*)(smc + OFF_BIAS);
    float*  sg    = (float*)(smc + OFF_G);
    float*  sbl   = (float*)(smc + OFF_BL);
    float*  qm    = (float*)(smc + OFF_QM);
    float*  sL    = (float*)(smc + OFF_SL);
    float*  slb   = (float*)(smc + OFF_SLB);

    const int tid  = threadIdx.x;
    const int lane = tid & 31;
    const int wid  = tid >> 5;
    const int bm   = blockIdx.y * 128;
    const int bn   = blockIdx.x * 256;
    const int wm   = (wid & 1) * 64;
    const int wn   = (wid >> 1) * 64;
    const int ln4  = lane >> 2;
    const int lnm  = lane & 3;
    const unsigned su = (unsigned)__cvta_generic_to_shared(smc);

    const int a_row = lane & 15;
    const int a_kq  = (lane >> 4) << 3;
    const int b_row = (lane & 7) + (((lane >> 4) & 1) << 3);
    const int b_kq  = ((lane >> 3) & 1) << 3;

    sbias[tid] = bias[bn + tid];
    if (EPI == 1) { sg[tid] = lng[tid]; sbl[tid] = lnbb[tid]; }

    if (ASRC == 1) {
        if (tid < 128) {
            const __half* hp = A + (size_t)(bm + tid) * EMB;
#pragma unroll
            for (int q = 0; q < 8; q++)
                qm[tid * 8 + q] = cosf(__half2float(hp[q])) * cosf(theta[q]);
        }
        if (tid < 128) {
            int rr = tid >> 1, hf = (tid & 1) * 4;
            *(float4*)(sL + rr * 8 + hf) = *(const float4*)(l1w + rr * 8 + hf);
        }
        if (tid < 64) slb[tid] = l1b[tid];
    }

    float acc[4][8][4];
#pragma unroll
    for (int i = 0; i < 4; i++)
#pragma unroll
        for (int j = 0; j < 8; j++)
#pragma unroll
            for (int t = 0; t < 4; t++) acc[i][j][t] = 0.f;

    const int nc = K >> 6;

    stage_chunk<ASRC>(A, W, smc, bm, bn, K, 0, 0, tid);
    cp_commit();
    if (ASRC == 1) {
        __syncthreads();
        compute_a_chunk64(smc, 0, 0, tid);
    }

    for (int c = 0; c < nc; c++) {
        const int buf = c & 1;
        const int nb  = buf ^ 1;
        if (c + 1 < nc) {
            stage_chunk<ASRC>(A, W, smc, bm, bn, K, c + 1, nb, tid);
            if (ASRC == 1) {
                if (tid < 128) {
                    int rr = tid >> 1, hf = (tid & 1) * 4;
                    *(float4*)(sL + ((c + 1) & 1) * 512 + rr * 8 + hf) =
                        *(const float4*)(l1w + ((size_t)(c + 1) * 64 + rr) * 8 + hf);
                }
                if (tid < 64) slb[((c + 1) & 1) * 64 + tid] = l1b[(c + 1) * 64 + tid];
            }
            cp_commit();
            cp_wait<1>();
        } else {
            cp_wait<0>();
        }
        __syncthreads();

        const unsigned abase = su + OFF_SA + buf * SA_BYTES;
        const unsigned bbase = su + OFF_SB + buf * SB_BYTES;

#pragma unroll
        for (int s = 0; s < 4; s++) {
            const int k0 = s * 16;
            unsigned af[4][4];
#pragma unroll
            for (int i = 0; i < 4; i++) {
                unsigned addr = abase +
                    ((wm + i * 16 + a_row) * GKH + k0 + a_kq) * 2;
                ldmx4(af[i][0], af[i][1], af[i][2], af[i][3], addr);
            }
#pragma unroll
            for (int j2 = 0; j2 < 4; j2++) {
                unsigned baddr = bbase +
                    ((wn + j2 * 16 + b_row) * GKH + k0 + b_kq) * 2;
                unsigned b0, b1, b2, b3;
                ldmx4(b0, b1, b2, b3, baddr);
#pragma unroll
                for (int i = 0; i < 4; i++) {
                    mma_f16(acc[i][2 * j2],     af[i], b0, b1);
                    mma_f16(acc[i][2 * j2 + 1], af[i], b2, b3);
                }
            }
        }

        if (ASRC == 1 && c + 1 < nc)
            compute_a_chunk64(smc, nb, (c + 1) & 1, tid);
        __syncthreads();
    }

    if (EPI == 0) {
#pragma unroll
        for (int i = 0; i < 4; i++) {
            const int gr0 = bm + wm + i * 16 + ln4;
#pragma unroll
            for (int j = 0; j < 8; j++) {
                const int col = wn + j * 8 + 2 * lnm;
                const float b0 = sbias[col], b1 = sbias[col + 1];
                *(__half2*)(C + (size_t)gr0 * N + bn + col) =
                    __floats2half2_rn(acc[i][j][0] + b0, acc[i][j][1] + b1);
                *(__half2*)(C + (size_t)(gr0 + 8) * N + bn + col) =
                    __floats2half2_rn(acc[i][j][2] + b0, acc[i][j][3] + b1);
            }
        }
    } else {
#pragma unroll
        for (int i = 0; i < 4; i++) {
            const int lr0 = wm + i * 16 + ln4;
            const int gr0 = bm + lr0;
            float s0 = 0.f, q0 = 0.f, s1 = 0.f, q1 = 0.f;
#pragma unroll
            for (int j = 0; j < 8; j++) {
                const int col = wn + j * 8 + 2 * lnm;
                const float b0 = sbias[col], b1 = sbias[col + 1];
                float2 r0 = __half22float2(*(const __half2*)(resid + (size_t)gr0 * 256 + col));
                float2 r1 = __half22float2(*(const __half2*)(resid + (size_t)(gr0 + 8) * 256 + col));
                float v0 = acc[i][j][0] + b0 + r0.x;
                float v1 = acc[i][j][1] + b1 + r0.y;
                float v2 = acc[i][j][2] + b0 + r1.x;
                float v3 = acc[i][j][3] + b1 + r1.y;
                acc[i][j][0] = v0; acc[i][j][1] = v1;
                acc[i][j][2] = v2; acc[i][j][3] = v3;
                s0 += v0 + v1; q0 += v0 * v0 + v1 * v1;
                s1 += v2 + v3; q1 += v2 * v2 + v3 * v3;
            }
#pragma unroll
            for (int o = 1; o <= 2; o <<= 1) {
                s0 += __shfl_xor_sync(0xffffffffu, s0, o);
                q0 += __shfl_xor_sync(0xffffffffu, q0, o);
                s1 += __shfl_xor_sync(0xffffffffu, s1, o);
                q1 += __shfl_xor_sync(0xffffffffu, q1, o);
            }
            if (lnm == 0) {
                sred[lr0 * 4 + (wid >> 1)]       = make_float2(s0, q0);
                sred[(lr0 + 8) * 4 + (wid >> 1)] = make_float2(s1, q1);
            }
        }
        __syncthreads();
#pragma unroll
        for (int i = 0; i < 4; i++) {
            const int lr0 = wm + i * 16 + ln4;
            const int gr0 = bm + lr0;
            float2 a0 = sred[lr0 * 4 + 0], a1 = sred[lr0 * 4 + 1];
            float2 a2 = sred[lr0 * 4 + 2], a3 = sred[lr0 * 4 + 3];
            float mean0 = (a0.x + a1.x + a2.x + a3.x) * (1.f / 256.f);
            float e0    = (a0.y + a1.y + a2.y + a3.y) * (1.f / 256.f);
            float rstd0 = rsqrtf(e0 - mean0 * mean0 + 1e-5f);
            float2 c0 = sred[(lr0 + 8) * 4 + 0], c1 = sred[(lr0 + 8) * 4 + 1];
            float2 c2 = sred[(lr0 + 8) * 4 + 2], c3 = sred[(lr0 + 8) * 4 + 3];
            float mean1 = (c0.x + c1.x + c2.x + c3.x) * (1.f / 256.f);
            float e1    = (c0.y + c1.y + c2.y + c3.y) * (1.f / 256.f);
            float rstd1 = rsqrtf(e1 - mean1 * mean1 + 1e-5f);
#pragma unroll
            for (int j = 0; j < 8; j++) {
                const int col = wn + j * 8 + 2 * lnm;
                const float g0 = sg[col], g1 = sg[col + 1];
                const float d0 = sbl[col], d1 = sbl[col + 1];
                *(__half2*)(C + (size_t)gr0 * 256 + col) = __floats2half2_rn(
                    (acc[i][j][0] - mean0) * rstd0 * g0 + d0,
                    (acc[i][j][1] - mean0) * rstd0 * g1 + d1);
                *(__half2*)(C + (size_t)(gr0 + 8) * 256 + col) = __floats2half2_rn(
                    (acc[i][j][2] - mean1) * rstd1 * g0 + d0,
                    (acc[i][j][3] - mean1) * rstd1 * g1 + d1);
            }
        }
    }
}

// ============================================================
// 4. fp16 tensor-core attention — online softmax, occ 2 (R11, exact)
// ============================================================
#define KS_ST 40
#define VT_ST 216
#define PS_ST 72

__global__ void __launch_bounds__(256, 2)
attention_h(const __half* __restrict__ qkv, __half* __restrict__ o)
{
    __shared__ __half Ks[208 * KS_ST];
    __shared__ __half Vt[32 * VT_ST];
    __shared__ __half Ps[8 * 16 * PS_ST];

    const int hh = blockIdx.x;
    const int b  = blockIdx.y;
    const int tid  = threadIdx.x;
    const int lane = tid & 31;
    const int wid  = tid >> 5;
    const int r    = lane >> 2;
    const int lq   = lane & 3;
    const float scale = 0.17677669529663687f;
    const __half* base = qkv + (size_t)b * SEQ * (3 * EMB) + hh * HDIM;

    const int a_row = lane & 15;
    const int a_kq  = (lane >> 4) << 3;
    const int b_row = (lane & 7) + (((lane >> 4) & 1) << 3);
    const int b_kq  = ((lane >> 3) & 1) << 3;

    for (int i = tid; i < 208 * 4; i += 256) {
        int s = i >> 2, sg = i & 3;
        float4 v = make_float4(0.f, 0.f, 0.f, 0.f);
        if (s < SEQ) v = *(const float4*)(base + (size_t)s * (3 * EMB) + EMB + sg * 8);
        *(float4*)(Ks + s * KS_ST + sg * 8) = v;
    }
    for (int i = tid; i < SEQ * 32; i += 256) {
        int s = i >> 5, d = i & 31;
        Vt[d * VT_ST + s] = base[(size_t)s * (3 * EMB) + 2 * EMB + d];
    }
    for (int i = tid; i < 32 * 20; i += 256) {
        int d = i / 20, c = SEQ + i % 20;
        Vt[d * VT_ST + c] = __float2half(0.f);
    }
    __syncthreads();

    __half* Pw = Ps + wid * 16 * PS_ST;
    const unsigned ks_su = (unsigned)__cvta_generic_to_shared(Ks);
    const unsigned vt_su = (unsigned)__cvta_generic_to_shared(Vt);
    const unsigned pw_su = (unsigned)__cvta_generic_to_shared(Pw);

    for (int strip = wid; strip < 13; strip += 8) {
        const int q0 = strip * 16 + r;
        const int q1 = q0 + 8;
        const int qa = q0 < SEQ ? q0 : SEQ - 1;
        const int qb = q1 < SEQ ? q1 : SEQ - 1;

        unsigned af[2][4];
#pragma unroll
        for (int kc = 0; kc < 2; kc++) {
            const __half* pa = base + (size_t)qa * (3 * EMB) + kc * 16 + 2 * lq;
            const __half* pc = base + (size_t)qb * (3 * EMB) + kc * 16 + 2 * lq;
            af[kc][0] = ldu(pa);
            af[kc][1] = ldu(pc);
            af[kc][2] = ldu(pa + 8);
            af[kc][3] = ldu(pc + 8);
        }

        float m0 = -1e30f, m1 = -1e30f;
        float l0 = 0.f,   l1 = 0.f;
        float O[4][4];
#pragma unroll
        for (int nt = 0; nt < 4; nt++) {
            O[nt][0] = 0.f; O[nt][1] = 0.f; O[nt][2] = 0.f; O[nt][3] = 0.f;
        }

#pragma unroll
        for (int ch = 0; ch < 4; ch++) {
            const int njg = (ch < 3) ? 8 : 2;
            const int njp = (ch < 3) ? 4 : 1;

            float acc[8][4];
#pragma unroll
            for (int jj = 0; jj < 8; jj++) {
                acc[jj][0] = 0.f; acc[jj][1] = 0.f;
                acc[jj][2] = 0.f; acc[jj][3] = 0.f;
            }
#pragma unroll
            for (int jpl = 0; jpl < 4; jpl++) {
                if (jpl < njp) {
                    const int jp = ch * 4 + jpl;
#pragma unroll
                    for (int kc = 0; kc < 2; kc++) {
                        unsigned baddr = ks_su +
                            ((jp * 16 + b_row) * KS_ST + kc * 16 + b_kq) * 2;
                        unsigned b0, b1, b2, b3;
                        ldmx4(b0, b1, b2, b3, baddr);
                        mma_f16(acc[2 * jpl],     af[kc], b0, b1);
                        mma_f16(acc[2 * jpl + 1], af[kc], b2, b3);
                    }
                }
            }
            if (ch == 3) {
                if (lq >= 2) {
                    acc[0][0] = -1e30f; acc[0][1] = -1e30f;
                    acc[0][2] = -1e30f; acc[0][3] = -1e30f;
                }
                acc[1][0] = -1e30f; acc[1][1] = -1e30f;
                acc[1][2] = -1e30f; acc[1][3] = -1e30f;
            }

            float lm0 = -1e30f, lm1 = -1e30f;
#pragma unroll
            for (int jj = 0; jj < 8; jj++) {
                if (jj < njg) {
                    lm0 = fmaxf(lm0, fmaxf(acc[jj][0], acc[jj][1]));
                    lm1 = fmaxf(lm1, fmaxf(acc[jj][2], acc[jj][3]));
                }
            }
            lm0 = fmaxf(lm0, __shfl_xor_sync(0xffffffffu, lm0, 1));
            lm0 = fmaxf(lm0, __shfl_xor_sync(0xffffffffu, lm0, 2));
            lm1 = fmaxf(lm1, __shfl_xor_sync(0xffffffffu, lm1, 1));
            lm1 = fmaxf(lm1, __shfl_xor_sync(0xffffffffu, lm1, 2));
            const float mn0 = fmaxf(m0, lm0);
            const float mn1 = fmaxf(m1, lm1);
            const float f0 = __expf((m0 - mn0) * scale);
            const float f1 = __expf((m1 - mn1) * scale);
            m0 = mn0; m1 = mn1;

            float s0 = 0.f, s1 = 0.f;
#pragma unroll
            for (int jj = 0; jj < 8; jj++) {
                if (jj < njg) {
                    acc[jj][0] = __expf((acc[jj][0] - mn0) * scale);
                    acc[jj][1] = __expf((acc[jj][1] - mn0) * scale);
                    acc[jj][2] = __expf((acc[jj][2] - mn1) * scale);
                    acc[jj][3] = __expf((acc[jj][3] - mn1) * scale);
                    s0 += acc[jj][0] + acc[jj][1];
                    s1 += acc[jj][2] + acc[jj][3];
                }
            }
            s0 += __shfl_xor_sync(0xffffffffu, s0, 1);
            s0 += __shfl_xor_sync(0xffffffffu, s0, 2);
            s1 += __shfl_xor_sync(0xffffffffu, s1, 1);
            s1 += __shfl_xor_sync(0xffffffffu, s1, 2);
            l0 = l0 * f0 + s0;
            l1 = l1 * f1 + s1;
#pragma unroll
            for (int nt = 0; nt < 4; nt++) {
                O[nt][0] *= f0; O[nt][1] *= f0;
                O[nt][2] *= f1; O[nt][3] *= f1;
            }

#pragma unroll
            for (int jj = 0; jj < 8; jj++) {
                if (jj < njg) {
                    *(__half2*)(Pw + r * PS_ST + jj * 8 + 2 * lq) =
                        __floats2half2_rn(acc[jj][0], acc[jj][1]);
                    *(__half2*)(Pw + (r + 8) * PS_ST + jj * 8 + 2 * lq) =
                        __floats2half2_rn(acc[jj][2], acc[jj][3]);
                }
            }
            __syncwarp();
            const int nkk = (ch < 3) ? 4 : 1;
#pragma unroll
            for (int kk = 0; kk < 4; kk++) {
                if (kk < nkk) {
                    unsigned pa[4];
                    unsigned paddr = pw_su + (a_row * PS_ST + kk * 16 + a_kq) * 2;
                    ldmx4(pa[0], pa[1], pa[2], pa[3], paddr);
#pragma unroll
                    for (int ntp = 0; ntp < 2; ntp++) {
                        unsigned vaddr = vt_su +
                            ((ntp * 16 + b_row) * VT_ST + ch * 64 + kk * 16 + b_kq) * 2;
                        unsigned b0, b1, b2, b3;
                        ldmx4(b0, b1, b2, b3, vaddr);
                        mma_f16(O[2 * ntp],     pa, b0, b1);
                        mma_f16(O[2 * ntp + 1], pa, b2, b3);
                    }
                }
            }
            __syncwarp();
        }

        const float inv0 = 1.f / l0;
        const float inv1 = 1.f / l1;

        if (q0 < SEQ) {
            __half* op = o + (size_t)(b * SEQ + q0) * EMB + hh * HDIM + 2 * lq;
#pragma unroll
            for (int nt = 0; nt < 4; nt++)
                *(__half2*)(op + nt * 8) =
                    __floats2half2_rn(O[nt][0] * inv0, O[nt][1] * inv0);
        }
        if (q1 < SEQ) {
            __half* op = o + (size_t)(b * SEQ + q1) * EMB + hh * HDIM + 2 * lq;
#pragma unroll
            for (int nt = 0; nt < 4; nt++)
                *(__half2*)(op + nt * 8) =
                    __floats2half2_rn(O[nt][2] * inv1, O[nt][3] * inv1);
        }
    }
}

// ============================================================
// 7. Mean-pool + classifier (h is fp16)
// ============================================================
__global__ void __launch_bounds__(256)
pool_cls_kernel(const __half* __restrict__ h, const float* __restrict__ cw,
                const float* __restrict__ cb, float* __restrict__ out)
{
    int b = blockIdx.x;
    int e = threadIdx.x;
    const __half* hp = h + (size_t)b * SEQ * EMB + e;
    float s = 0.f;
    for (int t = 0; t < SEQ; t++) s += __half2float(hp[(size_t)t * EMB]);
    __shared__ float sp[EMB];
    sp[e] = s * (1.f / 196.f);
    __syncthreads();
    if (e < NCLS) {
        float acc = cb[e];
        const float* w = cw + e * EMB;
        for (int k = 0; k < EMB; k++) acc += sp[k] * w[k];
        out[b * NCLS + e] = acc;
    }
}

// ============================================================
// launcher
// ============================================================
extern "C" void kernel_launch(void* const* d_in, const int* in_sizes, int n_in,
                              void* d_out, int out_size)
{
    const float* x    = (const float*)d_in[0];
    const float* qfw  = (const float*)d_in[1];
    const float* qfb  = (const float*)d_in[2];
    const float* pww  = (const float*)d_in[3];
    const float* pwb  = (const float*)d_in[4];
    const float* embw = (const float*)d_in[5];
    const float* embb = (const float*)d_in[6];
    const float* inw  = (const float*)d_in[7];
    const float* inb  = (const float*)d_in[8];
    const float* outw = (const float*)d_in[9];
    const float* outb = (const float*)d_in[10];
    const float* thet = (const float*)d_in[11];
    const float* l1w  = (const float*)d_in[12];
    const float* l1b  = (const float*)d_in[13];
    const float* l2w  = (const float*)d_in[14];
    const float* l2b  = (const float*)d_in[15];
    const float* ln1g = (const float*)d_in[16];
    const float* ln1b = (const float*)d_in[17];
    const float* ln2g = (const float*)d_in[18];
    const float* ln2b = (const float*)d_in[19];
    const float* clsw = (const float*)d_in[20];
    const float* clsb = (const float*)d_in[21];
    float* out = (float*)d_out;

    __half *h, *qkv, *attn, *w_in, *w_out, *w_l2;
    float *feat, *pe;
    cudaGetSymbolAddress((void**)&h,     g_h);
    cudaGetSymbolAddress((void**)&qkv,   g_qkv);
    cudaGetSymbolAddress((void**)&attn,  g_attn);
    cudaGetSymbolAddress((void**)&feat,  g_feat);
    cudaGetSymbolAddress((void**)&pe,    g_pe);
    cudaGetSymbolAddress((void**)&w_in,  g_w_in);
    cudaGetSymbolAddress((void**)&w_out, g_w_out);
    cudaGetSymbolAddress((void**)&w_l2,  g_w_l2);

    cudaFuncSetAttribute(gemm_h<0,0>,
                         cudaFuncAttributeMaxDynamicSharedMemorySize, SMEM_GH);
    cudaFuncSetAttribute(gemm_h<0,1>,
                         cudaFuncAttributeMaxDynamicSharedMemorySize, SMEM_GH);
    cudaFuncSetAttribute(gemm_h<1,1>,
                         cudaFuncAttributeMaxDynamicSharedMemorySize, SMEM_GH);

    const int n_in_w  = NBLK * 3 * EMB * EMB;
    const int n_out_w = NBLK * EMB * EMB;
    const int n_l2_w  = NBLK * EMB * FF;
    const int n_tot   = n_in_w + n_out_w + n_l2_w;
    wcvt_kernel<<<(n_tot + 255) / 256, 256>>>(inw, w_in, n_in_w,
                                              outw, w_out, n_out_w,
                                              l2w, w_l2, n_l2_w);
    pe_kernel<<<SEQ, EMB>>>(pe);

    quanv_kernel<<<(TOK * 4 + 255) / 256, 256>>>(x, qfw, qfb, pww, pwb, feat);
    embed_kernel<<<TOK / 4, 256>>>(feat, embw, embb, pe, h);

    for (int i = 0; i < NBLK; i++) {
        gemm_h<0,0><<<dim3(3, TOK / 128), 256, SMEM_GH>>>(
            h, w_in + (size_t)i * 3 * EMB * EMB, inb + (size_t)i * 3 * EMB,
            nullptr, nullptr, nullptr, nullptr, nullptr, nullptr,
            qkv, TOK, 3 * EMB, EMB);

        attention_h<<<dim3(HEADS, BATCH), 256>>>(qkv, attn);

        gemm_h<0,1><<<dim3(1, TOK / 128), 256, SMEM_GH>>>(
            attn, w_out + (size_t)i * EMB * EMB, outb + (size_t)i * EMB,
            h, ln1g + (size_t)i * EMB, ln1b + (size_t)i * EMB,
            nullptr, nullptr, nullptr,
            h, TOK, EMB, EMB);

        gemm_h<1,1><<<dim3(1, TOK / 128), 256, SMEM_GH>>>(
            h, w_l2 + (size_t)i * EMB * FF, l2b + (size_t)i * EMB,
            h, ln2g + (size_t)i * EMB, ln2b + (size_t)i * EMB,
            l1w + (size_t)i * FF * NQBIT, l1b + (size_t)i * FF,
            thet + (size_t)i * NQBIT,
            h, TOK, EMB, FF);
    }

    pool_cls_kernel<<<BATCH, 256>>>(h, clsw, clsb, out);
}